// round 13
// baseline (speedup 1.0000x reference)
#include <cuda_runtime.h>
#include <cuda_fp16.h>
#include <stdint.h>

#define N_NODES_MAX 100000
#define N_EDGES_MAX 1250000
#define D_FEAT 64
#define SCAN_B 1024
#define CH_EPT 4   // int4 chunks per thread in hist/fill (= 16 edges)

// ---- static scratch (no cudaMalloc allowed) ----
__device__ __half g_xh[(size_t)N_NODES_MAX * D_FEAT];    // x in fp16
__device__ __half g_th[(size_t)N_NODES_MAX * D_FEAT];    // relu(conv1) in fp16
__device__ int    g_deg[N_NODES_MAX];
__device__ int    g_rowptr[N_NODES_MAX + 1];
__device__ int    g_rank[N_EDGES_MAX];
__device__ int    g_src_sorted[N_EDGES_MAX];
__device__ int    g_scanagg[128];
__device__ int    g_scanflag[128];
__device__ int    g_idx_is64;   // 1 = int64 indices, 0 = int32

// ---- fused prologue: block 0 = dtype probe + scan-flag zero;
//      blocks [1,1+zb) = zero deg; blocks [1+zb, ...) = fp32->fp16 convert ----
__global__ void prologue_kernel(const unsigned int* __restrict__ w,
                                const float* __restrict__ x,
                                __half* __restrict__ xh,
                                int* __restrict__ deg,
                                int n_nodes, int n_floats, int zb) {
    int b = blockIdx.x;
    if (b == 0) {
        int nz = 0;
        #pragma unroll
        for (int k = 0; k < 4; ++k) {
            int i = threadIdx.x * 4 + k;
            if (w[2 * i + 1] != 0u) nz = 1;
        }
        int any = __syncthreads_or(nz);
        if (threadIdx.x == 0) g_idx_is64 = any ? 0 : 1;
        if (threadIdx.x < 128) { g_scanagg[threadIdx.x] = 0; g_scanflag[threadIdx.x] = 0; }
    } else if (b <= zb) {
        int i = (b - 1) * blockDim.x + threadIdx.x;
        if (i < n_nodes) deg[i] = 0;
    } else {
        int i = (b - 1 - zb) * blockDim.x + threadIdx.x;
        int base = i * 8;
        if (base + 7 < n_floats) {
            float4 a = *reinterpret_cast<const float4*>(x + base);
            float4 c = *reinterpret_cast<const float4*>(x + base + 4);
            __half2 h[4];
            h[0] = __floats2half2_rn(a.x, a.y);
            h[1] = __floats2half2_rn(a.z, a.w);
            h[2] = __floats2half2_rn(c.x, c.y);
            h[3] = __floats2half2_rn(c.z, c.w);
            *reinterpret_cast<uint4*>(xh + base) = *reinterpret_cast<uint4*>(h);
        } else if (base < n_floats) {
            for (int k = base; k < n_floats; ++k) xh[k] = __float2half_rn(x[k]);
        }
    }
}

// ---- histogram of dst; atomic return value = rank within dst segment ----
__global__ void hist_kernel(const void* __restrict__ ei, int* __restrict__ deg,
                            int* __restrict__ rank, int n_edges, int n_ct) {
    int is64 = g_idx_is64;
    int t = blockIdx.x * blockDim.x + threadIdx.x;
    if (t >= n_ct) return;
    if (!is64) {
        const int* dst = ((const int*)ei) + n_edges;
        int n_vec = n_edges >> 2;

        int c[CH_EPT]; bool v[CH_EPT]; int4 d[CH_EPT];
        #pragma unroll
        for (int k = 0; k < CH_EPT; ++k) {
            c[k] = t + k * n_ct;
            v[k] = (c[k] < n_vec);
            if (v[k]) d[k] = __ldg(((const int4*)dst) + c[k]);
        }
        int4 r[CH_EPT];
        #pragma unroll
        for (int k = 0; k < CH_EPT; ++k) {
            if (v[k]) {
                r[k].x = atomicAdd(&deg[d[k].x], 1);
                r[k].y = atomicAdd(&deg[d[k].y], 1);
                r[k].z = atomicAdd(&deg[d[k].z], 1);
                r[k].w = atomicAdd(&deg[d[k].w], 1);
            }
        }
        #pragma unroll
        for (int k = 0; k < CH_EPT; ++k)
            if (v[k]) *reinterpret_cast<int4*>(rank + c[k] * 4) = r[k];

        if (t == 0) {
            for (int e = n_vec * 4; e < n_edges; ++e)
                rank[e] = atomicAdd(&deg[__ldg(dst + e)], 1);
        }
    } else {
        const long long* dst = ((const long long*)ei) + n_edges;
        for (int k = 0; k < CH_EPT * 4; ++k) {
            long long e = (long long)t + (long long)k * n_ct * 4;
            if (e < n_edges) rank[e] = atomicAdd(&deg[(int)__ldg(dst + e)], 1);
        }
        if (t == 0) {
            for (long long e = (long long)n_ct * 4 * CH_EPT; e < n_edges; ++e)
                rank[e] = atomicAdd(&deg[(int)__ldg(dst + e)], 1);
        }
    }
}

// ---- single-kernel exclusive scan with aggregate lookback ----
// All <=98 blocks co-resident (1024 thr -> 2 blocks/SM capacity 296 >= 98),
// so spin-wait on lower-indexed blocks' aggregates is deadlock-free.
__global__ void scan_kernel(const int* __restrict__ deg, int* __restrict__ rowptr,
                            int n, int n_edges) {
    __shared__ int warp_sums[32];
    __shared__ int s_block_off;
    int t = threadIdx.x;
    int lane = t & 31, wid = t >> 5;
    int bid = blockIdx.x;
    int i = bid * SCAN_B + t;
    int v = (i < n) ? deg[i] : 0;
    int incl = v;
    #pragma unroll
    for (int off = 1; off < 32; off <<= 1) {
        int u = __shfl_up_sync(0xffffffffu, incl, off);
        if (lane >= off) incl += u;
    }
    if (lane == 31) warp_sums[wid] = incl;
    __syncthreads();
    if (wid == 0) {
        int ws = warp_sums[lane];
        int wincl = ws;
        #pragma unroll
        for (int off = 1; off < 32; off <<= 1) {
            int u = __shfl_up_sync(0xffffffffu, wincl, off);
            if (lane >= off) wincl += u;
        }
        warp_sums[lane] = wincl - ws;   // exclusive warp offsets
        // lane 31 holds block total -> publish aggregate
        if (lane == 31) {
            g_scanagg[bid] = wincl;
            __threadfence();
            atomicExch(&g_scanflag[bid], 1);
        }
        // lookback: sum aggregates of all preceding blocks
        int sum = 0;
        for (int base = 0; base < bid; base += 32) {
            int p = base + lane;
            int a = 0;
            if (p < bid) {
                while (atomicAdd(&g_scanflag[p], 0) == 0) {}
                a = g_scanagg[p];
            }
            #pragma unroll
            for (int off = 16; off > 0; off >>= 1)
                a += __shfl_down_sync(0xffffffffu, a, off);
            if (lane == 0) sum += a;
        }
        if (lane == 0) s_block_off = sum;
    }
    __syncthreads();
    if (i < n) rowptr[i] = incl - v + warp_sums[wid] + s_block_off;
    if (i == 0) rowptr[n] = n_edges;
}

// ---- fill dst-sorted src list (no atomics: rank precomputed) ----
__global__ void fill_kernel(const void* __restrict__ ei, const int* __restrict__ rowptr,
                            const int* __restrict__ rank, int* __restrict__ src_sorted,
                            int n_edges, int n_ct) {
    int is64 = g_idx_is64;
    int t = blockIdx.x * blockDim.x + threadIdx.x;
    if (t >= n_ct) return;
    if (!is64) {
        const int* srcp = (const int*)ei;
        const int* dstp = srcp + n_edges;
        int n_vec = n_edges >> 2;

        int c[CH_EPT]; bool v[CH_EPT];
        int4 s[CH_EPT], d[CH_EPT], r[CH_EPT];
        #pragma unroll
        for (int k = 0; k < CH_EPT; ++k) {
            c[k] = t + k * n_ct;
            v[k] = (c[k] < n_vec);
            if (v[k]) {
                s[k] = __ldg(((const int4*)srcp) + c[k]);
                d[k] = __ldg(((const int4*)dstp) + c[k]);
                r[k] = __ldg(((const int4*)rank) + c[k]);
            }
        }
        int4 p[CH_EPT];
        #pragma unroll
        for (int k = 0; k < CH_EPT; ++k) {
            if (v[k]) {
                p[k].x = __ldg(rowptr + d[k].x);
                p[k].y = __ldg(rowptr + d[k].y);
                p[k].z = __ldg(rowptr + d[k].z);
                p[k].w = __ldg(rowptr + d[k].w);
            }
        }
        #pragma unroll
        for (int k = 0; k < CH_EPT; ++k) {
            if (v[k]) {
                src_sorted[p[k].x + r[k].x] = s[k].x;
                src_sorted[p[k].y + r[k].y] = s[k].y;
                src_sorted[p[k].z + r[k].z] = s[k].z;
                src_sorted[p[k].w + r[k].w] = s[k].w;
            }
        }
        if (t == 0) {
            for (int e = n_vec * 4; e < n_edges; ++e)
                src_sorted[__ldg(rowptr + __ldg(dstp + e)) + __ldg(rank + e)] = __ldg(srcp + e);
        }
    } else {
        const long long* srcp = (const long long*)ei;
        for (int k = 0; k < CH_EPT * 4; ++k) {
            long long e = (long long)t + (long long)k * n_ct * 4;
            if (e < n_edges) {
                int s = (int)__ldg(srcp + e);
                int dd = (int)__ldg(srcp + n_edges + e);
                src_sorted[__ldg(rowptr + dd) + __ldg(rank + e)] = s;
            }
        }
        if (t == 0) {
            for (long long e = (long long)n_ct * 4 * CH_EPT; e < n_edges; ++e) {
                int s = (int)__ldg(srcp + e);
                int dd = (int)__ldg(srcp + n_edges + e);
                src_sorted[__ldg(rowptr + dd) + __ldg(rank + e)] = s;
            }
        }
    }
}

// ---- shared accumulate helper: 4-edge unrolled segment sum ----
// 8 threads per node; each thread owns 8 feature halves (16B uint4 load).
// 4 independent gathers in flight per iteration.
__device__ __forceinline__ void seg_accum(const __half* __restrict__ in,
                                          const int* __restrict__ src_sorted,
                                          int beg, int end, int lane, float* acc) {
    int j = beg;
    for (; j + 3 < end; j += 4) {
        int s0 = __ldg(src_sorted + j);
        int s1 = __ldg(src_sorted + j + 1);
        int s2 = __ldg(src_sorted + j + 2);
        int s3 = __ldg(src_sorted + j + 3);
        uint4 a0 = __ldg((const uint4*)(in + (size_t)s0 * D_FEAT) + lane);
        uint4 a1 = __ldg((const uint4*)(in + (size_t)s1 * D_FEAT) + lane);
        uint4 a2 = __ldg((const uint4*)(in + (size_t)s2 * D_FEAT) + lane);
        uint4 a3 = __ldg((const uint4*)(in + (size_t)s3 * D_FEAT) + lane);
        const __half2* h0 = (const __half2*)&a0;
        const __half2* h1 = (const __half2*)&a1;
        const __half2* h2 = (const __half2*)&a2;
        const __half2* h3 = (const __half2*)&a3;
        #pragma unroll
        for (int k = 0; k < 4; ++k) {
            float2 f0 = __half22float2(h0[k]);
            float2 f1 = __half22float2(h1[k]);
            float2 f2 = __half22float2(h2[k]);
            float2 f3 = __half22float2(h3[k]);
            acc[2 * k]     += (f0.x + f1.x) + (f2.x + f3.x);
            acc[2 * k + 1] += (f0.y + f1.y) + (f2.y + f3.y);
        }
    }
    for (; j < end; ++j) {
        int s = __ldg(src_sorted + j);
        uint4 a = __ldg((const uint4*)(in + (size_t)s * D_FEAT) + lane);
        const __half2* ha = (const __half2*)&a;
        #pragma unroll
        for (int k = 0; k < 4; ++k) {
            float2 fa = __half22float2(ha[k]);
            acc[2 * k]     += fa.x;
            acc[2 * k + 1] += fa.y;
        }
    }
}

// ---- aggregate pass 1: tmp_h[node] = half(relu(sum in_h[src])) ----
__global__ void agg1_kernel(const __half* __restrict__ in,
                            const int* __restrict__ rowptr,
                            const int* __restrict__ src_sorted,
                            __half* __restrict__ out, int n_nodes) {
    int node = blockIdx.x * (blockDim.x >> 3) + (threadIdx.x >> 3);
    int lane = threadIdx.x & 7;
    if (node >= n_nodes) return;
    int beg = __ldg(rowptr + node);
    int end = __ldg(rowptr + node + 1);

    float acc[8];
    #pragma unroll
    for (int k = 0; k < 8; ++k) acc[k] = 0.f;
    seg_accum(in, src_sorted, beg, end, lane, acc);

    __half2 r[4];
    #pragma unroll
    for (int k = 0; k < 4; ++k)
        r[k] = __floats2half2_rn(fmaxf(acc[2 * k], 0.f), fmaxf(acc[2 * k + 1], 0.f));
    *reinterpret_cast<uint4*>(out + (size_t)node * D_FEAT + lane * 8) =
        *reinterpret_cast<uint4*>(r);
}

// ---- aggregate pass 2: out_f32[node] = sum tmp_h[src] ----
__global__ void agg2_kernel(const __half* __restrict__ in,
                            const int* __restrict__ rowptr,
                            const int* __restrict__ src_sorted,
                            float* __restrict__ out, int n_nodes) {
    int node = blockIdx.x * (blockDim.x >> 3) + (threadIdx.x >> 3);
    int lane = threadIdx.x & 7;
    if (node >= n_nodes) return;
    int beg = __ldg(rowptr + node);
    int end = __ldg(rowptr + node + 1);

    float acc[8];
    #pragma unroll
    for (int k = 0; k < 8; ++k) acc[k] = 0.f;
    seg_accum(in, src_sorted, beg, end, lane, acc);

    float* op = out + (size_t)node * D_FEAT + lane * 8;
    *reinterpret_cast<float4*>(op)     = make_float4(acc[0], acc[1], acc[2], acc[3]);
    *reinterpret_cast<float4*>(op + 4) = make_float4(acc[4], acc[5], acc[6], acc[7]);
}

extern "C" void kernel_launch(void* const* d_in, const int* in_sizes, int n_in,
                              void* d_out, int out_size) {
    const float* x = (const float*)d_in[0];   // [N_NODES, 64] f32
    const void* ei = d_in[1];                 // [2, N_EDGES] i64 or i32

    int n_edges = in_sizes[1] / 2;
    if (n_edges > N_EDGES_MAX) n_edges = N_EDGES_MAX;
    int n_nodes = in_sizes[0] / D_FEAT;
    if (n_nodes > N_NODES_MAX) n_nodes = N_NODES_MAX;
    int n_node_floats = in_sizes[0];

    float* out = (float*)d_out;

    __half *xh, *th; int *deg, *rowptr, *rank, *src_sorted;
    cudaGetSymbolAddress((void**)&xh, g_xh);
    cudaGetSymbolAddress((void**)&th, g_th);
    cudaGetSymbolAddress((void**)&deg, g_deg);
    cudaGetSymbolAddress((void**)&rowptr, g_rowptr);
    cudaGetSymbolAddress((void**)&rank, g_rank);
    cudaGetSymbolAddress((void**)&src_sorted, g_src_sorted);

    // 1. fused prologue: dtype probe + scan-flag zero + deg zero + fp16 convert
    int zb = (n_nodes + 255) / 256;
    int cb = ((n_node_floats + 7) / 8 + 255) / 256;
    prologue_kernel<<<1 + zb + cb, 256>>>((const unsigned int*)ei, x, xh, deg,
                                          n_nodes, n_node_floats, zb);

    // 2. CSR build: histogram(+rank) -> single-kernel scan -> fill
    int n_vec = n_edges >> 2;
    int n_ct = (n_vec + CH_EPT - 1) / CH_EPT;
    if (n_ct < 1) n_ct = 1;
    hist_kernel<<<(n_ct + 255) / 256, 256>>>(ei, deg, rank, n_edges, n_ct);

    int nb = (n_nodes + SCAN_B - 1) / SCAN_B;   // <= 98 (all co-resident)
    scan_kernel<<<nb, SCAN_B>>>(deg, rowptr, n_nodes, n_edges);

    fill_kernel<<<(n_ct + 255) / 256, 256>>>(ei, rowptr, rank, src_sorted, n_edges, n_ct);

    // 3. two aggregation passes over fp16 features, fp32 accumulate
    int threads = 256;
    int nodes_per_block = threads / 8;
    int blocks = (n_nodes + nodes_per_block - 1) / nodes_per_block;

    agg1_kernel<<<blocks, threads>>>(xh, rowptr, src_sorted, th, n_nodes);
    agg2_kernel<<<blocks, threads>>>(th, rowptr, src_sorted, out, n_nodes);
}